// round 14
// baseline (speedup 1.0000x reference)
#include <cuda_runtime.h>
#include <cuda_bf16.h>
#include <cstdint>

// Problem constants (fixed by setup_inputs)
#define B_   8
#define NS   5
#define NQ   128
#define T_   16
#define D_   2048
#define NROWS (B_*NQ)           // 1024

__device__ float g_rowterm[NROWS];
__device__ unsigned int g_done;   // zero-init; last block resets

#define LAM 0.1f
#define INVLAM 10.0f

#define PSTRIDE 257
#define GT 640

// ---- smem layout ----
#define F32_STAGE 26624                 // 208 rows * 32 f32 * 4B
#define RING_BYTES (3*F32_STAGE)        // 79872 per K-group
#define OFF_FP8 (2*RING_BYTES)          // 159744
#define FP8_TILE 9984                   // 208 rows * 48B
#define STRIDE 48
#define BOFF (80*STRIDE)                // 3840
#define KG_FP8 (2*FP8_TILE)             // 19968
#define SMEM_BYTES (OFF_FP8 + 2*KG_FP8) // 199680

// overlay (inside group0 ring, used only after both mainloops + __syncthreads)
#define OV_NORM 42240                   // 208 f32
#define OV_T1   43072                   // 40 f32
#define OV_T2   43232                   // 40 f32
#define OV_SSP  43392                   // 2*1664 f32

__device__ __forceinline__ float softmin2(float a, float b) {
    float mn = fminf(a, b);
    return mn - LAM * __logf(1.0f + __expf(-fabsf(a - b) * INVLAM));
}
__device__ __forceinline__ float softmin3(float a, float b, float c) {
    float mn = fminf(fminf(a, b), c);
    float s = __expf((mn - a) * INVLAM) + __expf((mn - b) * INVLAM) + __expf((mn - c) * INVLAM);
    return mn - LAM * __logf(s);
}
__device__ __forceinline__ uint32_t smem_u32(const void* p) {
    uint32_t a;
    asm("{ .reg .u64 t; cvta.to.shared.u64 t, %1; cvt.u32.u64 %0, t; }" : "=r"(a) : "l"(p));
    return a;
}
__device__ __forceinline__ void ldsm4(uint32_t addr, uint32_t& r0, uint32_t& r1,
                                      uint32_t& r2, uint32_t& r3) {
    asm volatile("ldmatrix.sync.aligned.m8n8.x4.shared.b16 {%0,%1,%2,%3}, [%4];"
                 : "=r"(r0), "=r"(r1), "=r"(r2), "=r"(r3) : "r"(addr));
}
__device__ __forceinline__ void cpa16(uint32_t dst, const float* src) {
    asm volatile("cp.async.cg.shared.global [%0], [%1], 16;" :: "r"(dst), "l"(src));
}
// f32x4 -> packed e4m3x4 (one u32, byte k-order x,y,z,w)
__device__ __forceinline__ uint32_t cvt_e4(float4 v) {
    uint16_t lo, hi;
    asm("cvt.rn.satfinite.e4m3x2.f32 %0, %1, %2;" : "=h"(lo) : "f"(v.y), "f"(v.x));
    asm("cvt.rn.satfinite.e4m3x2.f32 %0, %1, %2;" : "=h"(hi) : "f"(v.w), "f"(v.z));
    uint32_t r;
    asm("mov.b32 %0, {%1, %2};" : "=r"(r) : "h"(lo), "h"(hi));
    return r;
}
#define DOT4(v) ((v).x*(v).x + (v).y*(v).y + (v).z*(v).z + (v).w*(v).w)
#define GBAR() asm volatile("bar.sync %0, %1;" :: "r"(kg + 1), "r"(320) : "memory")

// ---------------- fused kernel ----------------
// Block = (batch b, 128-query tile nt). Tile rows 0..79 supp, 80..207 query.
// Two K-groups of 320 threads; each: cp.async f32 ring (3 stages) ->
// cvt+sumsq -> fp8 tiles (2) -> m16n8k32 e4m3 MMA. 16 windows of 2 chunks.
__global__ __launch_bounds__(GT, 1) void gemm_dtw_kernel(
        const float* __restrict__ supp, const float* __restrict__ query,
        const int* __restrict__ ys, float* __restrict__ out) {
    extern __shared__ char smc[];
    float* accbuf = (float*)smc;                    // overlay: 10560 f32
    float* sDist  = accbuf;
    float* norm   = (float*)(smc + OV_NORM);
    float* t1s    = (float*)(smc + OV_T1);
    float* t2s    = (float*)(smc + OV_T2);
    float* ssp    = (float*)(smc + OV_SSP);         // [2][1664]

    const int b = blockIdx.y, nt = blockIdx.x;
    const int tid = threadIdx.x, wid = tid >> 5, lane = tid & 31;
    const int kg = wid >= 10;
    const int gtid = tid - kg * 320;
    const int gwid = wid - kg * 10;
    const uint32_t smb = smem_u32(smc);

    const int wm = gwid % 5;             // M warp tile (16 supp rows)
    const int wn = gwid / 5;             // N warp tile (64 query cols)
    const int g  = lane >> 2, t = lane & 3;
    const int quad = lane >> 3, qi = lane & 7;

    // per-group regions
    char* const ringG = smc + kg * RING_BYTES;
    const uint32_t ringU = smb + kg * RING_BYTES;
    char* const fp8G = smc + OFF_FP8 + kg * KG_FP8;
    const uint32_t fp8U = smb + OFF_FP8 + kg * KG_FP8;

    // ---- fp8 ldsm offsets within a tile (same as verified FP8 round) ----
    const uint32_t offA = (uint32_t)((wm*16 + (quad & 1)*8 + qi) * STRIDE + (quad >> 1) * 16);
    uint32_t offB[4];
    #pragma unroll
    for (int jj = 0; jj < 4; jj++)
        offB[jj] = (uint32_t)(BOFF + (wn*64 + (2*jj + (quad >> 1))*8 + qi) * STRIDE + (quad & 1) * 16);

    // ---- per-thread segments: seg s = gtid + 320k, k=0..5 (k=5 iff gtid<64) ----
    const float* gp[6];
    uint32_t fo[6];
    int po[6];
    bool act5;
    {
        #pragma unroll
        for (int k = 0; k < 6; k++) {
            const int s = gtid + 320*k;
            const bool a = (s < 1664);
            const int rr = a ? (s >> 3) : 0;
            const int cc = (s & 7) * 4;
            gp[k] = (rr < 80)
                ? supp  + ((size_t)b*80 + rr) * D_ + cc
                : query + ((size_t)b*2048 + nt*128 + (rr - 80)) * D_ + cc;
            fo[k] = (uint32_t)s * 16;
            po[k] = rr * STRIDE + cc;
        }
        act5 = (gtid < 64);
    }

    float acc[8][4];
    #pragma unroll
    for (int j = 0; j < 8; j++) { acc[j][0]=0.f; acc[j][1]=0.f; acc[j][2]=0.f; acc[j][3]=0.f; }
    float ss[6] = {0.f,0.f,0.f,0.f,0.f,0.f};

    // group chunk c (0..31) -> global K offset (kg + 2c)*32 floats
    #define ISSUE(c) do { \
        const uint32_t sb = ringU + (uint32_t)((c) % 3) * F32_STAGE; \
        const int kof = (kg + 2*(c)) * 32; \
        _Pragma("unroll") \
        for (int k = 0; k < 5; k++) cpa16(sb + fo[k], gp[k] + kof); \
        if (act5) cpa16(sb + fo[5], gp[5] + kof); \
        asm volatile("cp.async.commit_group;" ::: "memory"); } while(0)

    #define CVT(c, tsel) do { \
        const char* st = ringG + ((c) % 3) * F32_STAGE; \
        char* ft = fp8G + (tsel) * FP8_TILE; \
        _Pragma("unroll") \
        for (int k = 0; k < 5; k++) { \
            float4 v = *(const float4*)(st + fo[k]); \
            ss[k] += DOT4(v); \
            *(uint32_t*)(ft + po[k]) = cvt_e4(v); \
        } \
        if (act5) { \
            float4 v = *(const float4*)(st + fo[5]); \
            ss[5] += DOT4(v); \
            *(uint32_t*)(ft + po[5]) = cvt_e4(v); \
        } } while(0)

    #define MMA_SECTION(tsel) do { \
        const uint32_t base = fp8U + (uint32_t)(tsel) * FP8_TILE; \
        uint32_t a0, a1, a2, a3; \
        ldsm4(base + offA, a0, a1, a2, a3); \
        uint32_t bf[16]; \
        _Pragma("unroll") \
        for (int jj = 0; jj < 4; jj++) \
            ldsm4(base + offB[jj], bf[4*jj], bf[4*jj+1], bf[4*jj+2], bf[4*jj+3]); \
        _Pragma("unroll") \
        for (int j = 0; j < 8; j++) { \
            asm volatile( \
                "mma.sync.aligned.m16n8k32.row.col.f32.e4m3.e4m3.f32 " \
                "{%0,%1,%2,%3}, {%4,%5,%6,%7}, {%8,%9}, {%0,%1,%2,%3};\n" \
                : "+f"(acc[j][0]), "+f"(acc[j][1]), "+f"(acc[j][2]), "+f"(acc[j][3]) \
                : "r"(a0), "r"(a1), "r"(a2), "r"(a3), "r"(bf[2*j]), "r"(bf[2*j+1])); \
        } } while(0)

    // ---- prologue: chunks 0,1,2 in flight ----
    ISSUE(0); ISSUE(1); ISSUE(2);

    // ---- mainloop: 16 windows of 2 chunks ----
    #pragma unroll 1
    for (int w = 0; w < 16; w++) {
        if (w < 15) asm volatile("cp.async.wait_group 1;" ::: "memory");
        else        asm volatile("cp.async.wait_group 0;" ::: "memory");
        GBAR();                              // data visible; prev fp8 tiles consumed

        CVT(2*w, 0);
        if (2*w + 3 < 32) ISSUE(2*w + 3);    // reuses stage (2w)%3 (own segs only)
        CVT(2*w + 1, 1);
        if (2*w + 4 < 32) ISSUE(2*w + 4);    // reuses stage (2w+1)%3
        GBAR();                              // fp8 tiles ready

        MMA_SECTION(0);
        MMA_SECTION(1);
    }

    // ---- both groups done -> overlay is safe after full barrier ----
    __syncthreads();

    // norm partials (deterministic per-thread order)
    #pragma unroll
    for (int k = 0; k < 5; k++) ssp[kg*1664 + gtid + 320*k] = ss[k];
    if (act5) ssp[kg*1664 + gtid + 1600] = ss[5];

    // kg=1 dumps acc (stride-33 conflict-free)
    if (kg == 1) {
        float* ab = accbuf + gwid * 1056 + lane;
        #pragma unroll
        for (int j = 0; j < 8; j++)
            #pragma unroll
            for (int c = 0; c < 4; c++)
                ab[(j*4 + c) * 33] = acc[j][c];
    }
    __syncthreads();

    // kg=0: reduce partial acc; combine norms
    if (kg == 0) {
        const float* ab = accbuf + gwid * 1056 + lane;
        #pragma unroll
        for (int j = 0; j < 8; j++)
            #pragma unroll
            for (int c = 0; c < 4; c++)
                acc[j][c] += ab[(j*4 + c) * 33];
    }
    if (tid < 208) {
        const float* s0 = ssp + tid*8;
        const float* s1 = ssp + 1664 + tid*8;
        float v = 0.f;
        #pragma unroll
        for (int i = 0; i < 8; i++) v += s0[i] + s1[i];
        norm[tid] = rsqrtf(fmaxf(v, 1e-12f));
    }
    __syncthreads();

    // ---- dist epilogue (kg=0 only) ----
    if (kg == 0) {
        #pragma unroll
        for (int j = 0; j < 8; j++) {
            const int lc = wn * 64 + j * 8 + t * 2;
            #pragma unroll
            for (int half = 0; half < 2; half++) {
                const int lr = wm * 16 + g + half * 8;      // supp row 0..79
                const float invs = norm[lr];
                const int s = lr >> 4, l = lr & 15;
                #pragma unroll
                for (int e = 0; e < 2; e++) {
                    const int c = lc + e;                    // query col 0..127
                    const int ql = c >> 4, m = c & 15;
                    const int pb = ql * NS + s;
                    const float v = acc[j][half * 2 + e];
                    sDist[pb * PSTRIDE + (l << 4) + m] = 1.0f - v * invs * norm[80 + c];
                }
            }
        }
    }
    __syncthreads();

    // ---- soft-DTW: 80 threads, one (problem, direction) each ----
    if (tid < 80) {
        const int pb = tid >> 1, dir = tid & 1;
        const float* dm = sDist + pb * PSTRIDE;
        const int base = dir ? 255 : 0;
        const int sgn = dir ? -1 : 1;

        float prev[T_ + 2];
        prev[0] = 0.f;
        #pragma unroll
        for (int m = 1; m <= T_; m++) prev[m] = prev[m - 1] + dm[base + sgn * (m - 1)];
        prev[T_ + 1] = prev[T_];

        for (int l = 1; l < T_; l++) {
            const int rb = base + sgn * (l * 16);
            float drow[T_];
            #pragma unroll
            for (int m = 0; m < T_; m++) drow[m] = dm[rb + sgn * m];
            float left = 0.f;
            float dprev = prev[0];
            #pragma unroll
            for (int m = 1; m <= T_ + 1; m++) {
                const float up = prev[m];
                const float d = (m <= T_) ? drow[m - 1] : 0.f;
                float val;
                if (m == 1 || m == T_ + 1) val = softmin3(dprev, left, up) + d;
                else                        val = softmin2(dprev, left) + d;
                dprev = up;
                prev[m] = val;
                left = val;
            }
        }
        if (dir == 0) t1s[pb] = prev[T_ + 1];
        else          t2s[pb] = prev[T_ + 1];
    }
    __syncthreads();

    // ---- per-block outputs: tam + per-query CE term ----
    if (tid < 40) {
        const int qloc = tid / NS, s = tid % NS;
        const int row = b * NQ + nt * 8 + qloc;
        out[1 + row * NS + s] = 0.5f * (t1s[tid] + t2s[tid]);
    }
    if (tid < 8) {
        const int row = b * NQ + nt * 8 + tid;
        float t1[NS], t2[NS];
        #pragma unroll
        for (int s = 0; s < NS; s++) { t1[s] = t1s[tid * NS + s]; t2[s] = t2s[tid * NS + s]; }
        float mx1 = -t1[0], mx2 = -t2[0];
        #pragma unroll
        for (int s = 1; s < NS; s++) { mx1 = fmaxf(mx1, -t1[s]); mx2 = fmaxf(mx2, -t2[s]); }
        float se1 = 0.f, se2 = 0.f;
        #pragma unroll
        for (int s = 0; s < NS; s++) { se1 += __expf(-t1[s] - mx1); se2 += __expf(-t2[s] - mx2); }
        const int y = ys[row];
        g_rowterm[row] = (mx1 + __logf(se1) + t1[y]) + (mx2 + __logf(se2) + t2[y]);
    }

    // ---- last block computes the final loss ----
    __shared__ unsigned s_last;
    __shared__ float s_red[20];
    __threadfence();
    __syncthreads();
    if (tid == 0) s_last = (atomicAdd(&g_done, 1u) == 127u) ? 1u : 0u;
    __syncthreads();
    if (s_last) {
        float v = 0.f;
        if (tid < 512) v = g_rowterm[tid] + g_rowterm[tid + 512];
        #pragma unroll
        for (int o = 16; o; o >>= 1) v += __shfl_xor_sync(0xffffffffu, v, o);
        if (lane == 0 && wid < 16) s_red[wid] = v;
        __syncthreads();
        if (wid == 0) {
            float u = (lane < 16) ? s_red[lane] : 0.f;
            #pragma unroll
            for (int o = 8; o; o >>= 1) u += __shfl_xor_sync(0xffffffffu, u, o);
            if (lane == 0) { out[0] = 0.5f * u / (float)NROWS; g_done = 0u; }
        }
    }
}

// ---------------- launch ----------------
extern "C" void kernel_launch(void* const* d_in, const int* in_sizes, int n_in,
                              void* d_out, int out_size) {
    const float* supp  = (const float*)d_in[0];
    const float* query = (const float*)d_in[1];
    const int*   ys    = (const int*)d_in[2];
    float* out = (float*)d_out;

    static bool attr_set = false;
    if (!attr_set) {
        cudaFuncSetAttribute(gemm_dtw_kernel,
                             cudaFuncAttributeMaxDynamicSharedMemorySize, SMEM_BYTES);
        attr_set = true;
    }

    gemm_dtw_kernel<<<dim3(16, B_), GT, SMEM_BYTES>>>(supp, query, ys, out);
}

// round 15
// speedup vs baseline: 1.1238x; 1.1238x over previous
#include <cuda_runtime.h>
#include <cuda_bf16.h>
#include <cstdint>

// Problem constants (fixed by setup_inputs)
#define B_   8
#define NS   5
#define NQ   128
#define T_   16
#define D_   2048
#define NROWS (B_*NQ)           // 1024

__device__ float g_rowterm[NROWS];
__device__ unsigned int g_done;   // zero-init; last block resets

// softmin with fused exp2/log2 constants:
// C1 = 1/(lam*ln2), C2 = lam*ln2
#define C1 14.426950408889634f
#define C2 0.06931471805599453f

__device__ __forceinline__ float ex2f(float x) {
    float r; asm("ex2.approx.f32 %0, %1;" : "=f"(r) : "f"(x)); return r;
}
__device__ __forceinline__ float lg2f(float x) {
    float r; asm("lg2.approx.f32 %0, %1;" : "=f"(r) : "f"(x)); return r;
}
__device__ __forceinline__ float softmin2(float a, float b) {
    float mn = fminf(a, b);
    float e = ex2f(-fabsf(a - b) * C1);
    return fmaf(-C2, lg2f(1.0f + e), mn);
}
__device__ __forceinline__ float softmin3(float a, float b, float c) {
    float mn = fminf(fminf(a, b), c);
    float s = ex2f((mn - a) * C1) + ex2f((mn - b) * C1) + ex2f((mn - c) * C1);
    return fmaf(-C2, lg2f(s), mn);
}

__device__ __forceinline__ uint32_t smem_u32(const void* p) {
    uint32_t a;
    asm("{ .reg .u64 t; cvta.to.shared.u64 t, %1; cvt.u32.u64 %0, t; }" : "=r"(a) : "l"(p));
    return a;
}
__device__ __forceinline__ void ldsm4(uint32_t addr, uint32_t& r0, uint32_t& r1,
                                      uint32_t& r2, uint32_t& r3) {
    asm volatile("ldmatrix.sync.aligned.m8n8.x4.shared.b16 {%0,%1,%2,%3}, [%4];"
                 : "=r"(r0), "=r"(r1), "=r"(r2), "=r"(r3) : "r"(addr));
}
// f32x4 -> packed bf16x4 (two u32)
__device__ __forceinline__ uint2 cvt_u2(float4 v) {
    union { __nv_bfloat162 h; uint32_t u; } lo, hi;
    lo.h = __floats2bfloat162_rn(v.x, v.y);
    hi.h = __floats2bfloat162_rn(v.z, v.w);
    return make_uint2(lo.u, hi.u);
}

// ---------------- fused kernel: GEMM (split-K x2) -> cosine dist -> soft-DTW -> CE ----------------
#define BM 80
#define BN 128
#define BK 32
#define LDA 40        // smem row stride in bf16 (80 B)
#define GT 640        // 20 warps: 2 K-groups x (5 M x 2 N)
#define PSTRIDE 260   // 16B-aligned problem stride (40*260 = 10400 f32)

#define ABYTES (BM*LDA*2)         // 6400
#define BBYTES (BN*LDA*2)         // 10240
#define AB4 (4*ABYTES)            // per-kg A region (4 stages) 25600
#define BB4 (4*BBYTES)            // per-kg B region (4 stages) 40960
#define SB_BASE (2*AB4)           // 51200
#define OFF_ACC (SB_BASE + 2*BB4) // 133120

#define ACCBUF_F 10560
#define SMEM_BYTES (OFF_ACC + ACCBUF_F*4 + (256+160+80)*4)

__global__ __launch_bounds__(GT, 1) void gemm_dtw_kernel(
        const float* __restrict__ supp, const float* __restrict__ query,
        const int* __restrict__ ys, float* __restrict__ out) {
    extern __shared__ char smc[];
    float* accbuf = (float*)(smc + OFF_ACC);                  // 10560 f32 (later sDist)
    float* sDist  = accbuf;
    float* qsum   = accbuf + ACCBUF_F;                        // [2][128]
    float* ssum   = qsum + 256;                               // [2][80]
    float* t1s    = ssum + 160;                               // [40]
    float* t2s    = t1s + 40;                                 // [40]

    const int b = blockIdx.y, nt = blockIdx.x;
    const int tid = threadIdx.x, wid = tid >> 5, lane = tid & 31;
    const int kg = wid >= 10;            // K-split group
    const int gtid = tid - kg * 320;
    const int gwid = wid - kg * 10;
    const float* Ag = supp  + (size_t)b * BM * D_;
    const float* Bg = query + ((size_t)b * (NQ*T_) + (size_t)nt * BN) * D_;

    float acc[8][4];
    #pragma unroll
    for (int j = 0; j < 8; j++) { acc[j][0]=0.f; acc[j][1]=0.f; acc[j][2]=0.f; acc[j][3]=0.f; }

    const int wm = gwid % 5;             // M warp tile (16 rows)
    const int wn = gwid / 5;             // N warp tile (64 cols)
    const int g  = lane >> 2, t = lane & 3;
    const int quad = lane >> 3, qi = lane & 7;

    // ---- smem byte bases ----
    const uint32_t smb = smem_u32(smc);
    const uint32_t smbA = smb + kg * AB4;
    const uint32_t smbB = smb + SB_BASE + kg * BB4;
    char* const scA = smc + kg * AB4;
    char* const scB = smc + SB_BASE + kg * BB4;

    const uint32_t offA = (uint32_t)((wm*16 + qi + (quad & 1)*8) * (LDA*2) + (quad >> 1) * 16);
    uint32_t offB[4];
    #pragma unroll
    for (int jj = 0; jj < 4; jj++)
        offB[jj] = (uint32_t)((wn*64 + (2*jj + (quad >> 1))*8 + qi) * (LDA*2) + (quad & 1) * 16);

    // per-group loader coordinates (each row covered by one aligned 8-lane group)
    const int ar0 = gtid >> 3,        ac0 = (gtid & 7) * 4;
    const int ar1 = (gtid+320) >> 3,  ac1 = ((gtid+320) & 7) * 4;
    const int br0 = gtid >> 3,        bc0 = (gtid & 7) * 4;
    const int br1 = (gtid+320) >> 3,  bc1 = ((gtid+320) & 7) * 4;
    const int br2 = (gtid+640) >> 3,  bc2 = ((gtid+640) & 7) * 4;
    const int br3 = (gtid+960) >> 3,  bc3 = ((gtid+960) & 7) * 4;
    const bool b3ok = (gtid + 960) < BN * 8;

    float4 ra0, ra1, rb0, rb1, rb2, rb3;
    rb3.x = rb3.y = rb3.z = rb3.w = 0.f;

    float as0 = 0.f, as1 = 0.f, qs0 = 0.f, qs1 = 0.f, qs2 = 0.f, qs3 = 0.f;
    #define DOT4(v) ((v).x*(v).x + (v).y*(v).y + (v).z*(v).z + (v).w*(v).w)

    // supp: default caching (L2-resident reuse across nt-blocks);
    // query: streaming evict-first (each byte read once chip-wide)
    #define LDG_CHUNK(k0) do { \
        ra0 = *(const float4*)(Ag + (size_t)ar0*D_ + (k0) + ac0); \
        ra1 = *(const float4*)(Ag + (size_t)ar1*D_ + (k0) + ac1); \
        rb0 = __ldcs((const float4*)(Bg + (size_t)br0*D_ + (k0) + bc0)); \
        rb1 = __ldcs((const float4*)(Bg + (size_t)br1*D_ + (k0) + bc1)); \
        rb2 = __ldcs((const float4*)(Bg + (size_t)br2*D_ + (k0) + bc2)); \
        if (b3ok) rb3 = __ldcs((const float4*)(Bg + (size_t)br3*D_ + (k0) + bc3)); } while(0)

    #define SUMSQ_CHUNK() do { \
        as0 += DOT4(ra0); as1 += DOT4(ra1); \
        qs0 += DOT4(rb0); qs1 += DOT4(rb1); qs2 += DOT4(rb2); qs3 += DOT4(rb3); } while(0)

    #define STS_CHUNK(stg) do { \
        char* bA = scA + (stg) * ABYTES; \
        char* bB = scB + (stg) * BBYTES; \
        *(uint2*)(bA + (ar0*LDA + ac0)*2) = cvt_u2(ra0); \
        *(uint2*)(bA + (ar1*LDA + ac1)*2) = cvt_u2(ra1); \
        *(uint2*)(bB + (br0*LDA + bc0)*2) = cvt_u2(rb0); \
        *(uint2*)(bB + (br1*LDA + bc1)*2) = cvt_u2(rb1); \
        *(uint2*)(bB + (br2*LDA + bc2)*2) = cvt_u2(rb2); \
        if (b3ok) *(uint2*)(bB + (br3*LDA + bc3)*2) = cvt_u2(rb3); } while(0)

    #define MMA_SECTION(stg) do { \
        const uint32_t aB = smbA + (uint32_t)(stg) * ABYTES + offA; \
        const uint32_t bB = smbB + (uint32_t)(stg) * BBYTES; \
        _Pragma("unroll") \
        for (int ks = 0; ks < 2; ks++) { \
            uint32_t a0, a1, a2, a3; \
            ldsm4(aB + ks * 32, a0, a1, a2, a3); \
            uint32_t bf[16]; \
            _Pragma("unroll") \
            for (int jj = 0; jj < 4; jj++) \
                ldsm4(bB + offB[jj] + ks * 32, bf[4*jj], bf[4*jj+1], bf[4*jj+2], bf[4*jj+3]); \
            _Pragma("unroll") \
            for (int j = 0; j < 8; j++) { \
                asm volatile( \
                    "mma.sync.aligned.m16n8k16.row.col.f32.bf16.bf16.f32 " \
                    "{%0,%1,%2,%3}, {%4,%5,%6,%7}, {%8,%9}, {%0,%1,%2,%3};\n" \
                    : "+f"(acc[j][0]), "+f"(acc[j][1]), "+f"(acc[j][2]), "+f"(acc[j][3]) \
                    : "r"(a0), "r"(a1), "r"(a2), "r"(a3), "r"(bf[2*j]), "r"(bf[2*j+1])); \
            } \
        } } while(0)

    #define GBAR() asm volatile("bar.sync %0, %1;" :: "r"(kg + 1), "r"(320) : "memory")

    // group chunk c (0..31) sits at global K offset (kg + 2c)*BK

    // ---- prologue: chunks 0,1 staged; chunk 2 in regs ----
    LDG_CHUNK(kg * BK);
    SUMSQ_CHUNK();
    STS_CHUNK(0);
    LDG_CHUNK((kg + 2) * BK);
    SUMSQ_CHUNK();
    STS_CHUNK(1);
    LDG_CHUNK((kg + 4) * BK);
    GBAR();

    // ---- mainloop: 16 double-chunk iterations, one barrier each ----
    #pragma unroll 1
    for (int i = 0; i < 16; i++) {
        if (i < 15) {                     // stage chunk 2i+2 (regs from prev iter)
            SUMSQ_CHUNK();
            STS_CHUNK((2*i + 2) & 3);
            LDG_CHUNK((kg + 2*(2*i + 3)) * BK);
        }
        MMA_SECTION((2*i) & 3);
        if (i < 15) {                     // stage chunk 2i+3 (regs from this iter)
            SUMSQ_CHUNK();
            STS_CHUNK((2*i + 3) & 3);
        }
        if (i < 14) LDG_CHUNK((kg + 2*(2*i + 4)) * BK);
        MMA_SECTION((2*i + 1) & 3);
        GBAR();
    }

    // ---- per-group deterministic 8-lane reduction of sum-of-squares ----
    #pragma unroll
    for (int o = 4; o; o >>= 1) {
        as0 += __shfl_xor_sync(0xffffffffu, as0, o);
        as1 += __shfl_xor_sync(0xffffffffu, as1, o);
        qs0 += __shfl_xor_sync(0xffffffffu, qs0, o);
        qs1 += __shfl_xor_sync(0xffffffffu, qs1, o);
        qs2 += __shfl_xor_sync(0xffffffffu, qs2, o);
        qs3 += __shfl_xor_sync(0xffffffffu, qs3, o);
    }
    if ((gtid & 7) == 0) {
        ssum[kg*80 + ar0] = as0; ssum[kg*80 + ar1] = as1;
        qsum[kg*128 + br0] = qs0; qsum[kg*128 + br1] = qs1; qsum[kg*128 + br2] = qs2;
        if (b3ok) qsum[kg*128 + br3] = qs3;
    }

    // ---- kg=1 dumps acc (stride-33 conflict-free layout) ----
    if (kg == 1) {
        float* ab = accbuf + gwid * 1056 + lane;
        #pragma unroll
        for (int j = 0; j < 8; j++)
            #pragma unroll
            for (int c = 0; c < 4; c++)
                ab[(j*4 + c) * 33] = acc[j][c];
    }
    __syncthreads();

    // ---- kg=0: reduce + combine norms ----
    if (kg == 0) {
        const float* ab = accbuf + gwid * 1056 + lane;
        #pragma unroll
        for (int j = 0; j < 8; j++)
            #pragma unroll
            for (int c = 0; c < 4; c++)
                acc[j][c] += ab[(j*4 + c) * 33];
    }
    if (tid < BN)            qsum[tid] = rsqrtf(fmaxf(qsum[tid] + qsum[128 + tid], 1e-12f));
    else if (tid < BN + BM)  ssum[tid - BN] = rsqrtf(fmaxf(ssum[tid - BN] + ssum[80 + tid - BN], 1e-12f));
    __syncthreads();

    // ---- epilogue: dist into smem (kg=0 only) ----
    if (kg == 0) {
        #pragma unroll
        for (int j = 0; j < 8; j++) {
            const int lc = wn * 64 + j * 8 + t * 2;
            #pragma unroll
            for (int half = 0; half < 2; half++) {
                const int lr = wm * 16 + g + half * 8;      // 0..79
                const float invs = ssum[lr];
                const int s = lr >> 4, l = lr & 15;
                #pragma unroll
                for (int e = 0; e < 2; e++) {
                    const int c = lc + e;                    // local col 0..127
                    const int qloc = c >> 4, m = c & 15;
                    const int pb = qloc * NS + s;            // 0..39
                    const float v = acc[j][half * 2 + e];
                    sDist[pb * PSTRIDE + (l << 4) + m] = 1.0f - v * invs * qsum[c];
                }
            }
        }
    }
    __syncthreads();

    // ---- soft-DTW: 80 threads, one (problem, direction) each ----
    if (tid < 80) {
        const int pb = tid >> 1, dir = tid & 1;
        const float* dm = sDist + pb * PSTRIDE;

        // vectorized row loader: logical row l, direction-aware, register-reversed
        #define LOADROW(l, dr) do { \
            const float4* rp = (const float4*)(dm + (dir ? (240 - 16*(l)) : (16*(l)))); \
            float4 v0 = rp[0], v1 = rp[1], v2 = rp[2], v3 = rp[3]; \
            float rv[16] = {v0.x,v0.y,v0.z,v0.w, v1.x,v1.y,v1.z,v1.w, \
                            v2.x,v2.y,v2.z,v2.w, v3.x,v3.y,v3.z,v3.w}; \
            _Pragma("unroll") \
            for (int m = 0; m < 16; m++) dr[m] = dir ? rv[15 - m] : rv[m]; \
        } while(0)

        float prev[T_ + 2];
        {
            float dr0[16];
            LOADROW(0, dr0);
            prev[0] = 0.f;
            #pragma unroll
            for (int m = 1; m <= T_; m++) prev[m] = prev[m - 1] + dr0[m - 1];
            prev[T_ + 1] = prev[T_];
        }

        for (int l = 1; l < T_; l++) {
            float drow[16];
            LOADROW(l, drow);
            float left = 0.f;
            float dprev = prev[0];
            #pragma unroll
            for (int m = 1; m <= T_ + 1; m++) {
                const float up = prev[m];
                const float d = (m <= T_) ? drow[m - 1] : 0.f;
                float val;
                if (m == 1 || m == T_ + 1) val = softmin3(dprev, left, up) + d;
                else                        val = softmin2(dprev, left) + d;
                dprev = up;
                prev[m] = val;
                left = val;
            }
        }
        if (dir == 0) t1s[pb] = prev[T_ + 1];
        else          t2s[pb] = prev[T_ + 1];
    }
    __syncthreads();

    // ---- per-block outputs: tam + per-query CE term ----
    if (tid < 40) {
        const int qloc = tid / NS, s = tid % NS;
        const int row = b * NQ + nt * 8 + qloc;
        out[1 + row * NS + s] = 0.5f * (t1s[tid] + t2s[tid]);
    }
    if (tid < 8) {
        const int row = b * NQ + nt * 8 + tid;
        float t1[NS], t2[NS];
        #pragma unroll
        for (int s = 0; s < NS; s++) { t1[s] = t1s[tid * NS + s]; t2[s] = t2s[tid * NS + s]; }
        float mx1 = -t1[0], mx2 = -t2[0];
        #pragma unroll
        for (int s = 1; s < NS; s++) { mx1 = fmaxf(mx1, -t1[s]); mx2 = fmaxf(mx2, -t2[s]); }
        float se1 = 0.f, se2 = 0.f;
        #pragma unroll
        for (int s = 0; s < NS; s++) { se1 += __expf(-t1[s] - mx1); se2 += __expf(-t2[s] - mx2); }
        const int y = ys[row];
        g_rowterm[row] = (mx1 + __logf(se1) + t1[y]) + (mx2 + __logf(se2) + t2[y]);
    }

    // ---- last block computes the final loss ----
    __shared__ unsigned s_last;
    __shared__ float s_red[20];
    __threadfence();
    __syncthreads();
    if (tid == 0) s_last = (atomicAdd(&g_done, 1u) == 127u) ? 1u : 0u;
    __syncthreads();
    if (s_last) {
        float v = 0.f;
        if (tid < 512) v = g_rowterm[tid] + g_rowterm[tid + 512];
        #pragma unroll
        for (int o = 16; o; o >>= 1) v += __shfl_xor_sync(0xffffffffu, v, o);
        if (lane == 0 && wid < 16) s_red[wid] = v;
        __syncthreads();
        if (wid == 0) {
            float u = (lane < 16) ? s_red[lane] : 0.f;
            #pragma unroll
            for (int o = 8; o; o >>= 1) u += __shfl_xor_sync(0xffffffffu, u, o);
            if (lane == 0) { out[0] = 0.5f * u / (float)NROWS; g_done = 0u; }
        }
    }
}

// ---------------- launch ----------------
extern "C" void kernel_launch(void* const* d_in, const int* in_sizes, int n_in,
                              void* d_out, int out_size) {
    const float* supp  = (const float*)d_in[0];
    const float* query = (const float*)d_in[1];
    const int*   ys    = (const int*)d_in[2];
    float* out = (float*)d_out;

    static bool attr_set = false;
    if (!attr_set) {
        cudaFuncSetAttribute(gemm_dtw_kernel,
                             cudaFuncAttributeMaxDynamicSharedMemorySize, SMEM_BYTES);
        attr_set = true;
    }

    gemm_dtw_kernel<<<dim3(16, B_), GT, SMEM_BYTES>>>(supp, query, ys, out);
}

// round 16
// speedup vs baseline: 1.2139x; 1.0802x over previous
#include <cuda_runtime.h>
#include <cuda_bf16.h>
#include <cstdint>

// Problem constants (fixed by setup_inputs)
#define B_   8
#define NS   5
#define NQ   128
#define T_   16
#define D_   2048
#define NROWS (B_*NQ)           // 1024

__device__ float g_rowterm[NROWS];
__device__ unsigned int g_done;   // zero-init; last block resets

// softmin with fused exp2/log2 constants:
// C1 = 1/(lam*ln2), C2 = lam*ln2
#define C1 14.426950408889634f
#define C2 0.06931471805599453f

__device__ __forceinline__ float ex2f(float x) {
    float r; asm("ex2.approx.f32 %0, %1;" : "=f"(r) : "f"(x)); return r;
}
__device__ __forceinline__ float lg2f(float x) {
    float r; asm("lg2.approx.f32 %0, %1;" : "=f"(r) : "f"(x)); return r;
}
__device__ __forceinline__ float softmin2(float a, float b) {
    float mn = fminf(a, b);
    float e = ex2f(-fabsf(a - b) * C1);
    return fmaf(-C2, lg2f(1.0f + e), mn);
}
__device__ __forceinline__ float softmin3(float a, float b, float c) {
    float mn = fminf(fminf(a, b), c);
    float s = ex2f((mn - a) * C1) + ex2f((mn - b) * C1) + ex2f((mn - c) * C1);
    return fmaf(-C2, lg2f(s), mn);
}

__device__ __forceinline__ uint32_t smem_u32(const void* p) {
    uint32_t a;
    asm("{ .reg .u64 t; cvta.to.shared.u64 t, %1; cvt.u32.u64 %0, t; }" : "=r"(a) : "l"(p));
    return a;
}
__device__ __forceinline__ void ldsm4(uint32_t addr, uint32_t& r0, uint32_t& r1,
                                      uint32_t& r2, uint32_t& r3) {
    asm volatile("ldmatrix.sync.aligned.m8n8.x4.shared.b16 {%0,%1,%2,%3}, [%4];"
                 : "=r"(r0), "=r"(r1), "=r"(r2), "=r"(r3) : "r"(addr));
}
// f32x4 -> packed bf16x4 (two u32)
__device__ __forceinline__ uint2 cvt_u2(float4 v) {
    union { __nv_bfloat162 h; uint32_t u; } lo, hi;
    lo.h = __floats2bfloat162_rn(v.x, v.y);
    hi.h = __floats2bfloat162_rn(v.z, v.w);
    return make_uint2(lo.u, hi.u);
}

// ---------------- fused kernel: GEMM (split-K x2) -> cosine dist -> soft-DTW -> CE ----------------
#define BM 80
#define BN 128
#define BK 32
#define LDA 40        // smem row stride in bf16 (80 B)
#define GT 640        // 20 warps: 2 K-groups x (5 M x 2 N)
#define PSTRIDE 260   // 16B-aligned problem stride

#define ABYTES (BM*LDA*2)         // 6400
#define BBYTES (BN*LDA*2)         // 10240
#define AB4 (4*ABYTES)            // per-kg A region (4 stages) 25600
#define BB4 (4*BBYTES)            // per-kg B region (4 stages) 40960
#define SB_BASE (2*AB4)           // 51200
#define OFF_ACC (SB_BASE + 2*BB4) // 133120

#define ACCBUF_F 10560
#define SMEM_BYTES (OFF_ACC + ACCBUF_F*4 + (256+160+80)*4)

__global__ __launch_bounds__(GT, 1) void gemm_dtw_kernel(
        const float* __restrict__ supp, const float* __restrict__ query,
        const int* __restrict__ ys, float* __restrict__ out) {
    extern __shared__ char smc[];
    float* accbuf = (float*)(smc + OFF_ACC);                  // 10560 f32 (later sDist)
    float* sDist  = accbuf;
    float* qsum   = accbuf + ACCBUF_F;                        // [2][128]
    float* ssum   = qsum + 256;                               // [2][80]
    float* t1s    = ssum + 160;                               // [40]
    float* t2s    = t1s + 40;                                 // [40]

    const int b = blockIdx.y, nt = blockIdx.x;
    const int tid = threadIdx.x, wid = tid >> 5, lane = tid & 31;
    const int kg = wid >= 10;            // K-split group
    const int gtid = tid - kg * 320;
    const int gwid = wid - kg * 10;
    const float* Ag = supp  + (size_t)b * BM * D_;
    const float* Bg = query + ((size_t)b * (NQ*T_) + (size_t)nt * BN) * D_;

    float acc[8][4];
    #pragma unroll
    for (int j = 0; j < 8; j++) { acc[j][0]=0.f; acc[j][1]=0.f; acc[j][2]=0.f; acc[j][3]=0.f; }

    const int wm = gwid % 5;             // M warp tile (16 rows)
    const int wn = gwid / 5;             // N warp tile (64 cols)
    const int g  = lane >> 2, t = lane & 3;
    const int quad = lane >> 3, qi = lane & 7;

    // ---- smem byte bases ----
    const uint32_t smb = smem_u32(smc);
    const uint32_t smbA = smb + kg * AB4;
    const uint32_t smbB = smb + SB_BASE + kg * BB4;
    char* const scA = smc + kg * AB4;
    char* const scB = smc + SB_BASE + kg * BB4;

    const uint32_t offA = (uint32_t)((wm*16 + qi + (quad & 1)*8) * (LDA*2) + (quad >> 1) * 16);
    uint32_t offB[4];
    #pragma unroll
    for (int jj = 0; jj < 4; jj++)
        offB[jj] = (uint32_t)((wn*64 + (2*jj + (quad >> 1))*8 + qi) * (LDA*2) + (quad & 1) * 16);

    // per-group loader coordinates (each row covered by one aligned 8-lane group)
    const int ar0 = gtid >> 3,        ac0 = (gtid & 7) * 4;
    const int ar1 = (gtid+320) >> 3,  ac1 = ((gtid+320) & 7) * 4;
    const int br0 = gtid >> 3,        bc0 = (gtid & 7) * 4;
    const int br1 = (gtid+320) >> 3,  bc1 = ((gtid+320) & 7) * 4;
    const int br2 = (gtid+640) >> 3,  bc2 = ((gtid+640) & 7) * 4;
    const int br3 = (gtid+960) >> 3,  bc3 = ((gtid+960) & 7) * 4;
    const bool b3ok = (gtid + 960) < BN * 8;

    float4 ra0, ra1, rb0, rb1, rb2, rb3;
    rb3.x = rb3.y = rb3.z = rb3.w = 0.f;

    float as0 = 0.f, as1 = 0.f, qs0 = 0.f, qs1 = 0.f, qs2 = 0.f, qs3 = 0.f;
    #define DOT4(v) ((v).x*(v).x + (v).y*(v).y + (v).z*(v).z + (v).w*(v).w)

    // supp: default caching (L2-resident reuse); query: streaming evict-first
    #define LDG_CHUNK(k0) do { \
        ra0 = *(const float4*)(Ag + (size_t)ar0*D_ + (k0) + ac0); \
        ra1 = *(const float4*)(Ag + (size_t)ar1*D_ + (k0) + ac1); \
        rb0 = __ldcs((const float4*)(Bg + (size_t)br0*D_ + (k0) + bc0)); \
        rb1 = __ldcs((const float4*)(Bg + (size_t)br1*D_ + (k0) + bc1)); \
        rb2 = __ldcs((const float4*)(Bg + (size_t)br2*D_ + (k0) + bc2)); \
        if (b3ok) rb3 = __ldcs((const float4*)(Bg + (size_t)br3*D_ + (k0) + bc3)); } while(0)

    #define SUMSQ_CHUNK() do { \
        as0 += DOT4(ra0); as1 += DOT4(ra1); \
        qs0 += DOT4(rb0); qs1 += DOT4(rb1); qs2 += DOT4(rb2); qs3 += DOT4(rb3); } while(0)

    #define STS_CHUNK(stg) do { \
        char* bA = scA + (stg) * ABYTES; \
        char* bB = scB + (stg) * BBYTES; \
        *(uint2*)(bA + (ar0*LDA + ac0)*2) = cvt_u2(ra0); \
        *(uint2*)(bA + (ar1*LDA + ac1)*2) = cvt_u2(ra1); \
        *(uint2*)(bB + (br0*LDA + bc0)*2) = cvt_u2(rb0); \
        *(uint2*)(bB + (br1*LDA + bc1)*2) = cvt_u2(rb1); \
        *(uint2*)(bB + (br2*LDA + bc2)*2) = cvt_u2(rb2); \
        if (b3ok) *(uint2*)(bB + (br3*LDA + bc3)*2) = cvt_u2(rb3); } while(0)

    #define MMA_SECTION(stg) do { \
        const uint32_t aB = smbA + (uint32_t)(stg) * ABYTES + offA; \
        const uint32_t bB = smbB + (uint32_t)(stg) * BBYTES; \
        _Pragma("unroll") \
        for (int ks = 0; ks < 2; ks++) { \
            uint32_t a0, a1, a2, a3; \
            ldsm4(aB + ks * 32, a0, a1, a2, a3); \
            uint32_t bf[16]; \
            _Pragma("unroll") \
            for (int jj = 0; jj < 4; jj++) \
                ldsm4(bB + offB[jj] + ks * 32, bf[4*jj], bf[4*jj+1], bf[4*jj+2], bf[4*jj+3]); \
            _Pragma("unroll") \
            for (int j = 0; j < 8; j++) { \
                asm volatile( \
                    "mma.sync.aligned.m16n8k16.row.col.f32.bf16.bf16.f32 " \
                    "{%0,%1,%2,%3}, {%4,%5,%6,%7}, {%8,%9}, {%0,%1,%2,%3};\n" \
                    : "+f"(acc[j][0]), "+f"(acc[j][1]), "+f"(acc[j][2]), "+f"(acc[j][3]) \
                    : "r"(a0), "r"(a1), "r"(a2), "r"(a3), "r"(bf[2*j]), "r"(bf[2*j+1])); \
            } \
        } } while(0)

    #define GBAR() asm volatile("bar.sync %0, %1;" :: "r"(kg + 1), "r"(320) : "memory")

    // group chunk c (0..31) sits at global K offset (kg + 2c)*BK

    // ---- prologue: chunks 0,1 staged; chunk 2 in regs ----
    LDG_CHUNK(kg * BK);
    SUMSQ_CHUNK();
    STS_CHUNK(0);
    LDG_CHUNK((kg + 2) * BK);
    SUMSQ_CHUNK();
    STS_CHUNK(1);
    LDG_CHUNK((kg + 4) * BK);
    GBAR();

    // ---- mainloop: 16 double-chunk iterations, one barrier each ----
    #pragma unroll 1
    for (int i = 0; i < 16; i++) {
        if (i < 15) {                     // stage chunk 2i+2 (regs from prev iter)
            SUMSQ_CHUNK();
            STS_CHUNK((2*i + 2) & 3);
            LDG_CHUNK((kg + 2*(2*i + 3)) * BK);
        }
        MMA_SECTION((2*i) & 3);
        if (i < 15) {                     // stage chunk 2i+3 (regs from this iter)
            SUMSQ_CHUNK();
            STS_CHUNK((2*i + 3) & 3);
        }
        if (i < 14) LDG_CHUNK((kg + 2*(2*i + 4)) * BK);
        MMA_SECTION((2*i + 1) & 3);
        GBAR();
    }

    // ---- per-group deterministic 8-lane reduction of sum-of-squares ----
    #pragma unroll
    for (int o = 4; o; o >>= 1) {
        as0 += __shfl_xor_sync(0xffffffffu, as0, o);
        as1 += __shfl_xor_sync(0xffffffffu, as1, o);
        qs0 += __shfl_xor_sync(0xffffffffu, qs0, o);
        qs1 += __shfl_xor_sync(0xffffffffu, qs1, o);
        qs2 += __shfl_xor_sync(0xffffffffu, qs2, o);
        qs3 += __shfl_xor_sync(0xffffffffu, qs3, o);
    }
    if ((gtid & 7) == 0) {
        ssum[kg*80 + ar0] = as0; ssum[kg*80 + ar1] = as1;
        qsum[kg*128 + br0] = qs0; qsum[kg*128 + br1] = qs1; qsum[kg*128 + br2] = qs2;
        if (b3ok) qsum[kg*128 + br3] = qs3;
    }

    // ---- kg=1 dumps acc (stride-33 conflict-free layout) ----
    if (kg == 1) {
        float* ab = accbuf + gwid * 1056 + lane;
        #pragma unroll
        for (int j = 0; j < 8; j++)
            #pragma unroll
            for (int c = 0; c < 4; c++)
                ab[(j*4 + c) * 33] = acc[j][c];
    }
    __syncthreads();

    // ---- kg=0: reduce + combine norms ----
    if (kg == 0) {
        const float* ab = accbuf + gwid * 1056 + lane;
        #pragma unroll
        for (int j = 0; j < 8; j++)
            #pragma unroll
            for (int c = 0; c < 4; c++)
                acc[j][c] += ab[(j*4 + c) * 33];
    }
    if (tid < BN)            qsum[tid] = rsqrtf(fmaxf(qsum[tid] + qsum[128 + tid], 1e-12f));
    else if (tid < BN + BM)  ssum[tid - BN] = rsqrtf(fmaxf(ssum[tid - BN] + ssum[80 + tid - BN], 1e-12f));
    __syncthreads();

    // ---- epilogue: dist into smem (kg=0 only) ----
    if (kg == 0) {
        #pragma unroll
        for (int j = 0; j < 8; j++) {
            const int lc = wn * 64 + j * 8 + t * 2;
            #pragma unroll
            for (int half = 0; half < 2; half++) {
                const int lr = wm * 16 + g + half * 8;      // 0..79
                const float invs = ssum[lr];
                const int s = lr >> 4, l = lr & 15;
                #pragma unroll
                for (int e = 0; e < 2; e++) {
                    const int c = lc + e;                    // local col 0..127
                    const int qloc = c >> 4, m = c & 15;
                    const int pb = qloc * NS + s;            // 0..39
                    const float v = acc[j][half * 2 + e];
                    sDist[pb * PSTRIDE + (l << 4) + m] = 1.0f - v * invs * qsum[c];
                }
            }
        }
    }
    __syncthreads();

    // ---- soft-DTW: anti-diagonal wavefront, 8 lanes per (problem, direction) ----
    // unit u = tid>>3 (0..79): pb = u>>1, dir = u&1; lane j = tid&7 owns cols m=2j+1, 2j+2
    // (lane 7 also the m=17 boundary). Step s: lane j computes row l = s - j.
    {
        const int j = tid & 7, u = tid >> 3;
        const int pb = u >> 1, dir = u & 1;
        const float* dm = sDist + pb * PSTRIDE;
        const int base = dir ? 255 : 0;
        const int sgn = dir ? -1 : 1;
        #define EL(l, mm) dm[base + sgn * (16*(l) + (mm))]

        // row 0: 8-lane inclusive scan of pair sums
        float d0a = EL(0, 2*j), d0b = EL(0, 2*j + 1);
        const float pairs = d0a + d0b;
        float pre = pairs;
        #pragma unroll
        for (int o = 1; o < 8; o <<= 1) {
            float v = __shfl_up_sync(0xffffffffu, pre, o, 8);
            if (j >= o) pre += v;
        }
        float cur1 = pre - d0b;    // opt[0][2j+1]
        float cur2 = pre;          // opt[0][2j+2]
        float cur3 = pre;          // lane 7: opt[0][17] = opt[0][16]
        float old2 = cur2;         // one generation back (row l-2 col2 during loop)

        #pragma unroll 1
        for (int s = 1; s <= 22; s++) {
            const float nl = __shfl_up_sync(0xffffffffu, cur2, 1, 8);  // opt[l][2j]
            const float nd = __shfl_up_sync(0xffffffffu, old2, 1, 8);  // opt[l-1][2j]
            const int l = s - j;
            if (l >= 1 && l <= 15) {
                float v1;
                if (j == 0) v1 = softmin3(0.f, 0.f, cur1) + EL(l, 0);
                else        v1 = softmin2(nd, nl) + EL(l, 2*j);
                const float v2 = softmin2(cur1, v1) + EL(l, 2*j + 1);
                if (j == 7) cur3 = softmin3(cur2, v2, cur3);   // m=17 boundary, d=0
                old2 = cur2;
                cur1 = v1;
                cur2 = v2;
            }
        }
        if (j == 7) {
            if (dir == 0) t1s[pb] = cur3;
            else          t2s[pb] = cur3;
        }
        #undef EL
    }
    __syncthreads();

    // ---- per-block outputs: tam + per-query CE term ----
    if (tid < 40) {
        const int qloc = tid / NS, s = tid % NS;
        const int row = b * NQ + nt * 8 + qloc;
        out[1 + row * NS + s] = 0.5f * (t1s[tid] + t2s[tid]);
    }
    if (tid < 8) {
        const int row = b * NQ + nt * 8 + tid;
        float t1[NS], t2[NS];
        #pragma unroll
        for (int s = 0; s < NS; s++) { t1[s] = t1s[tid * NS + s]; t2[s] = t2s[tid * NS + s]; }
        float mx1 = -t1[0], mx2 = -t2[0];
        #pragma unroll
        for (int s = 1; s < NS; s++) { mx1 = fmaxf(mx1, -t1[s]); mx2 = fmaxf(mx2, -t2[s]); }
        float se1 = 0.f, se2 = 0.f;
        #pragma unroll
        for (int s = 0; s < NS; s++) { se1 += __expf(-t1[s] - mx1); se2 += __expf(-t2[s] - mx2); }
        const int y = ys[row];
        g_rowterm[row] = (mx1 + __logf(se1) + t1[y]) + (mx2 + __logf(se2) + t2[y]);
    }

    // ---- last block computes the final loss ----
    __shared__ unsigned s_last;
    __shared__ float s_red[20];
    __threadfence();
    __syncthreads();
    if (tid == 0) s_last = (atomicAdd(&g_done, 1u) == 127u) ? 1u : 0u;
    __syncthreads();
    if (s_last) {
        float v = 0.f;
        if (tid < 512) v = g_rowterm[tid] + g_rowterm[tid + 512];
        #pragma unroll
        for (int o = 16; o; o >>= 1) v += __shfl_xor_sync(0xffffffffu, v, o);
        if (lane == 0 && wid < 16) s_red[wid] = v;
        __syncthreads();
        if (wid == 0) {
            float u = (lane < 16) ? s_red[lane] : 0.f;
            #pragma unroll
            for (int o = 8; o; o >>= 1) u += __shfl_xor_sync(0xffffffffu, u, o);
            if (lane == 0) { out[0] = 0.5f * u / (float)NROWS; g_done = 0u; }
        }
    }
}

// ---------------- launch ----------------
extern "C" void kernel_launch(void* const* d_in, const int* in_sizes, int n_in,
                              void* d_out, int out_size) {
    const float* supp  = (const float*)d_in[0];
    const float* query = (const float*)d_in[1];
    const int*   ys    = (const int*)d_in[2];
    float* out = (float*)d_out;

    static bool attr_set = false;
    if (!attr_set) {
        cudaFuncSetAttribute(gemm_dtw_kernel,
                             cudaFuncAttributeMaxDynamicSharedMemorySize, SMEM_BYTES);
        attr_set = true;
    }

    gemm_dtw_kernel<<<dim3(16, B_), GT, SMEM_BYTES>>>(supp, query, ys, out);
}